// round 1
// baseline (speedup 1.0000x reference)
#include <cuda_runtime.h>

#define NQ 8192
#define NM 4096
#define ED 512
// log2(e) / TEMPERATURE  (TEMPERATURE = sqrt(512) = 22.627416997969522)
#define SM_SCALE (1.4426950408889634f / 22.627416997969522f)

// Scratch for projected tensors (allocation-free rule: __device__ globals)
__device__ float g_vq[NQ * ED];
__device__ float g_vk[NQ * ED];
__device__ float g_vv[NQ * ED];
__device__ float g_ok[NM * ED];
__device__ float g_ov[NM * ED];

// ---------------------------------------------------------------------------
// Projection GEMM: Y[r][c] = sum_e X[r][e] * W[c][e]   (y = x @ W^T)
// 128x128 block tile, BK=16, 256 threads, 8x8 register tile.
// Both smem tiles stored k-major [k][m] so inner loop reads are LDS.128.
// ---------------------------------------------------------------------------
__global__ __launch_bounds__(256) void proj_kernel(
    const float* __restrict__ X, const float* __restrict__ W, float* __restrict__ Y)
{
    const int BK = 16;
    __shared__ float As[BK][128 + 4];   // As[k][r]
    __shared__ float Bs[BK][128 + 4];   // Bs[k][c]
    int bm = blockIdx.x * 128;
    int bn = blockIdx.y * 128;
    int tid = threadIdx.x;
    int ty = tid >> 4, tx = tid & 15;

    float acc[8][8];
#pragma unroll
    for (int i = 0; i < 8; i++)
#pragma unroll
        for (int j = 0; j < 8; j++) acc[i][j] = 0.f;

    for (int k0 = 0; k0 < ED; k0 += BK) {
#pragma unroll
        for (int it = 0; it < 2; it++) {
            int idx = tid + it * 256;           // 0..511
            int row = idx & 127;                // lane-major rows -> conflict-free STS
            int k4  = (idx >> 7) << 2;          // 0,4,8,12
            float4 a = *(const float4*)(X + (bm + row) * ED + k0 + k4);
            As[k4 + 0][row] = a.x; As[k4 + 1][row] = a.y;
            As[k4 + 2][row] = a.z; As[k4 + 3][row] = a.w;
            float4 b = *(const float4*)(W + (bn + row) * ED + k0 + k4);
            Bs[k4 + 0][row] = b.x; Bs[k4 + 1][row] = b.y;
            Bs[k4 + 2][row] = b.z; Bs[k4 + 3][row] = b.w;
        }
        __syncthreads();
#pragma unroll
        for (int k = 0; k < BK; k++) {
            float4 a0 = *(const float4*)&As[k][ty * 8];
            float4 a1 = *(const float4*)&As[k][ty * 8 + 4];
            float4 b0 = *(const float4*)&Bs[k][tx * 8];
            float4 b1 = *(const float4*)&Bs[k][tx * 8 + 4];
            float av[8] = {a0.x, a0.y, a0.z, a0.w, a1.x, a1.y, a1.z, a1.w};
            float bv[8] = {b0.x, b0.y, b0.z, b0.w, b1.x, b1.y, b1.z, b1.w};
#pragma unroll
            for (int i = 0; i < 8; i++)
#pragma unroll
                for (int j = 0; j < 8; j++)
                    acc[i][j] += av[i] * bv[j];
        }
        __syncthreads();
    }
#pragma unroll
    for (int i = 0; i < 8; i++) {
        float* yp = Y + (bm + ty * 8 + i) * ED + bn + tx * 8;
        *(float4*)(yp)     = make_float4(acc[i][0], acc[i][1], acc[i][2], acc[i][3]);
        *(float4*)(yp + 4) = make_float4(acc[i][4], acc[i][5], acc[i][6], acc[i][7]);
    }
}

// ---------------------------------------------------------------------------
// Fused attention + softmax + weighted sum + self-term + residual + layernorm.
// One block = 64 query rows. Accumulator [64][512] fp32 lives in smem.
// Fixed softmax max = 0 (logits/T ~ N(0,1), bounded) -> no rescaling pass.
// ---------------------------------------------------------------------------
__global__ __launch_bounds__(256) void attn_kernel(
    const float* __restrict__ v_code,
    const float* __restrict__ gamma,
    const float* __restrict__ beta,
    float* __restrict__ out)
{
    extern __shared__ float smf[];
    float* accs = smf;                  // [64][512]
    float* Qs   = accs + 64 * 512;      // [64 e][68]  (k-major, padded)
    float* Ks   = Qs + 64 * 68;         // [64 e][68]
    float* Vs   = Ks + 64 * 68;         // [64 kv][64] (natural)
    float* Ps   = Vs + 64 * 64;         // [64 kv][68] (k-major)
    float* lsum = Ps + 64 * 68;         // [64]

    int tid = threadIdx.x;
    int ty = tid >> 4, tx = tid & 15;
    int bm = blockIdx.x * 64;

    for (int i = tid; i < 64 * 512; i += 256) accs[i] = 0.f;
    if (tid < 64) lsum[tid] = 0.f;
    __syncthreads();

    for (int kv0 = 0; kv0 < NM; kv0 += 64) {
        // ---- S = Q @ K^T over full E, accumulated in registers -------------
        float s[4][4];
#pragma unroll
        for (int i = 0; i < 4; i++)
#pragma unroll
            for (int j = 0; j < 4; j++) s[i][j] = 0.f;

        for (int ec = 0; ec < ED; ec += 64) {
#pragma unroll
            for (int it = 0; it < 4; it++) {
                int idx = tid + it * 256;       // 0..1023
                int r  = idx & 63;
                int e4 = (idx >> 6) << 2;       // 0..60
                float4 q = *(const float4*)(g_vq + (bm + r) * ED + ec + e4);
                Qs[(e4 + 0) * 68 + r] = q.x; Qs[(e4 + 1) * 68 + r] = q.y;
                Qs[(e4 + 2) * 68 + r] = q.z; Qs[(e4 + 3) * 68 + r] = q.w;
                float4 kk = *(const float4*)(g_ok + (kv0 + r) * ED + ec + e4);
                Ks[(e4 + 0) * 68 + r] = kk.x; Ks[(e4 + 1) * 68 + r] = kk.y;
                Ks[(e4 + 2) * 68 + r] = kk.z; Ks[(e4 + 3) * 68 + r] = kk.w;
            }
            __syncthreads();
#pragma unroll 8
            for (int e = 0; e < 64; e++) {
                float4 a = *(const float4*)&Qs[e * 68 + ty * 4];
                float4 b = *(const float4*)&Ks[e * 68 + tx * 4];
                s[0][0] += a.x * b.x; s[0][1] += a.x * b.y; s[0][2] += a.x * b.z; s[0][3] += a.x * b.w;
                s[1][0] += a.y * b.x; s[1][1] += a.y * b.y; s[1][2] += a.y * b.z; s[1][3] += a.y * b.w;
                s[2][0] += a.z * b.x; s[2][1] += a.z * b.y; s[2][2] += a.z * b.z; s[2][3] += a.z * b.w;
                s[3][0] += a.w * b.x; s[3][1] += a.w * b.y; s[3][2] += a.w * b.z; s[3][3] += a.w * b.w;
            }
            __syncthreads();
        }

        // ---- softmax numerators (fixed max = 0) + row sums -----------------
        float rsum[4] = {0.f, 0.f, 0.f, 0.f};
#pragma unroll
        for (int i = 0; i < 4; i++)
#pragma unroll
            for (int j = 0; j < 4; j++) {
                float p = exp2f(s[i][j] * SM_SCALE);
                s[i][j] = p;
                rsum[i] += p;
            }
#pragma unroll
        for (int o = 1; o < 16; o <<= 1)
#pragma unroll
            for (int i = 0; i < 4; i++)
                rsum[i] += __shfl_xor_sync(0xffffffffu, rsum[i], o);
        if (tx == 0) {
#pragma unroll
            for (int i = 0; i < 4; i++) lsum[ty * 4 + i] += rsum[i];
        }
        // store P transposed [kv][row] (A-operand of PV GEMM)
#pragma unroll
        for (int i = 0; i < 4; i++)
#pragma unroll
            for (int j = 0; j < 4; j++)
                Ps[(tx * 4 + j) * 68 + ty * 4 + i] = s[i][j];
        __syncthreads();

        // ---- acc += P @ V, E in 64-wide chunks ----------------------------
        for (int ec = 0; ec < ED; ec += 64) {
#pragma unroll
            for (int it = 0; it < 4; it++) {
                int idx = tid + it * 256;
                int r  = idx >> 4;
                int c4 = (idx & 15) << 2;
                *(float4*)&Vs[r * 64 + c4] =
                    *(const float4*)(g_ov + (kv0 + r) * ED + ec + c4);
            }
            __syncthreads();
            float c[4][4];
#pragma unroll
            for (int i = 0; i < 4; i++)
#pragma unroll
                for (int j = 0; j < 4; j++) c[i][j] = 0.f;
#pragma unroll 8
            for (int kv = 0; kv < 64; kv++) {
                float4 a = *(const float4*)&Ps[kv * 68 + ty * 4];
                float4 b = *(const float4*)&Vs[kv * 64 + tx * 4];
                c[0][0] += a.x * b.x; c[0][1] += a.x * b.y; c[0][2] += a.x * b.z; c[0][3] += a.x * b.w;
                c[1][0] += a.y * b.x; c[1][1] += a.y * b.y; c[1][2] += a.y * b.z; c[1][3] += a.y * b.w;
                c[2][0] += a.z * b.x; c[2][1] += a.z * b.y; c[2][2] += a.z * b.z; c[2][3] += a.z * b.w;
                c[3][0] += a.w * b.x; c[3][1] += a.w * b.y; c[3][2] += a.w * b.z; c[3][3] += a.w * b.w;
            }
#pragma unroll
            for (int i = 0; i < 4; i++) {
                float4* ap = (float4*)&accs[(ty * 4 + i) * 512 + ec + tx * 4];
                float4 v = *ap;
                v.x += c[i][0]; v.y += c[i][1]; v.z += c[i][2]; v.w += c[i][3];
                *ap = v;
            }
            __syncthreads();
        }
    }
    __syncthreads();

    // ---- epilogue: self-attention term, normalize, residual, layernorm ----
    int warp = tid >> 5, lane = tid & 31;
    for (int r = warp; r < 64; r += 8) {
        int R = bm + r;
        const float* q  = g_vq + R * ED;
        const float* kk = g_vk + R * ED;
        float sd = 0.f;
#pragma unroll
        for (int t = 0; t < 16; t++) { int e = lane + 32 * t; sd += q[e] * kk[e]; }
#pragma unroll
        for (int o = 16; o > 0; o >>= 1) sd += __shfl_xor_sync(0xffffffffu, sd, o);
        float pself = exp2f(sd * SM_SCALE);
        float linv = 1.f / (lsum[r] + pself);
        const float* vv = g_vv + R * ED;
        const float* vc = v_code + R * ED;
        float vals[16];
        float mu = 0.f;
#pragma unroll
        for (int t = 0; t < 16; t++) {
            int e = lane + 32 * t;
            float v = (accs[r * 512 + e] + pself * vv[e]) * linv + vc[e];
            vals[t] = v; mu += v;
        }
#pragma unroll
        for (int o = 16; o > 0; o >>= 1) mu += __shfl_xor_sync(0xffffffffu, mu, o);
        mu *= (1.f / 512.f);
        float var = 0.f;
#pragma unroll
        for (int t = 0; t < 16; t++) { float d = vals[t] - mu; var += d * d; }
#pragma unroll
        for (int o = 16; o > 0; o >>= 1) var += __shfl_xor_sync(0xffffffffu, var, o);
        float rstd = rsqrtf(var * (1.f / 512.f) + 1e-6f);
#pragma unroll
        for (int t = 0; t < 16; t++) {
            int e = lane + 32 * t;
            out[R * ED + e] = (vals[t] - mu) * rstd * gamma[e] + beta[e];
        }
    }
}

// ---------------------------------------------------------------------------
extern "C" void kernel_launch(void* const* d_in, const int* in_sizes, int n_in,
                              void* d_out, int out_size)
{
    const float* v_code   = (const float*)d_in[0];
    const float* obs_code = (const float*)d_in[1];
    const float* Wq       = (const float*)d_in[2];
    const float* Wk       = (const float*)d_in[3];
    const float* Wv       = (const float*)d_in[4];
    const float* gamma    = (const float*)d_in[5];
    const float* beta     = (const float*)d_in[6];
    float* out = (float*)d_out;

    float *vq, *vk, *vv, *ok, *ov;
    cudaGetSymbolAddress((void**)&vq, g_vq);
    cudaGetSymbolAddress((void**)&vk, g_vk);
    cudaGetSymbolAddress((void**)&vv, g_vv);
    cudaGetSymbolAddress((void**)&ok, g_ok);
    cudaGetSymbolAddress((void**)&ov, g_ov);

    dim3 blk(256);
    proj_kernel<<<dim3(NQ / 128, ED / 128), blk>>>(v_code, Wq, vq);
    proj_kernel<<<dim3(NQ / 128, ED / 128), blk>>>(v_code, Wk, vk);
    proj_kernel<<<dim3(NQ / 128, ED / 128), blk>>>(v_code, Wv, vv);
    proj_kernel<<<dim3(NM / 128, ED / 128), blk>>>(obs_code, Wk, ok);
    proj_kernel<<<dim3(NM / 128, ED / 128), blk>>>(obs_code, Wv, ov);

    int smem = (64 * 512 + 3 * 64 * 68 + 64 * 64 + 64) * 4;   // 199936 B
    cudaFuncSetAttribute(attn_kernel, cudaFuncAttributeMaxDynamicSharedMemorySize, smem);
    attn_kernel<<<NQ / 64, blk, smem>>>(v_code, gamma, beta, out);
}

// round 2
// speedup vs baseline: 1.5622x; 1.5622x over previous
#include <cuda_runtime.h>
#include <cuda_fp16.h>

#define NQ 8192
#define NM 4096
#define ED 512
// log2(e) / TEMPERATURE  (TEMPERATURE = sqrt(512))
#define SM_SCALE (1.4426950408889634f / 22.627416997969522f)

// Scratch (allocation-free rule: __device__ globals)
__device__ float g_vq[NQ * ED];
__device__ float g_vk[NQ * ED];
__device__ float g_vv[NQ * ED];
__device__ float g_ok[NM * ED];
__device__ float g_ov[NM * ED];
__device__ float g_O [NQ * ED];
__device__ uint4 g_P4[(size_t)NQ * NM / 8];   // P as fp16 [NQ][NM]

// ---------------------------------------------------------------------------
// Projection GEMM: Y[r][c] = sum_e X[r][e] * W[c][e]   (y = x @ W^T)
// 128x128 tile, BK=16, 256 threads, 8x8 register tile, k-major smem.
// ---------------------------------------------------------------------------
__global__ __launch_bounds__(256, 2) void proj_kernel(
    const float* __restrict__ X, const float* __restrict__ W, float* __restrict__ Y)
{
    __shared__ float As[16][132];
    __shared__ float Bs[16][132];
    int bm = blockIdx.x * 128;
    int bn = blockIdx.y * 128;
    int tid = threadIdx.x;
    int ty = tid >> 4, tx = tid & 15;

    float acc[8][8];
#pragma unroll
    for (int i = 0; i < 8; i++)
#pragma unroll
        for (int j = 0; j < 8; j++) acc[i][j] = 0.f;

    for (int k0 = 0; k0 < ED; k0 += 16) {
#pragma unroll
        for (int it = 0; it < 2; it++) {
            int idx = tid + it * 256;
            int row = idx & 127;
            int k4  = (idx >> 7) << 2;
            float4 a = *(const float4*)(X + (bm + row) * ED + k0 + k4);
            As[k4 + 0][row] = a.x; As[k4 + 1][row] = a.y;
            As[k4 + 2][row] = a.z; As[k4 + 3][row] = a.w;
            float4 b = *(const float4*)(W + (bn + row) * ED + k0 + k4);
            Bs[k4 + 0][row] = b.x; Bs[k4 + 1][row] = b.y;
            Bs[k4 + 2][row] = b.z; Bs[k4 + 3][row] = b.w;
        }
        __syncthreads();
#pragma unroll
        for (int k = 0; k < 16; k++) {
            float4 a0 = *(const float4*)&As[k][ty * 8];
            float4 a1 = *(const float4*)&As[k][ty * 8 + 4];
            float4 b0 = *(const float4*)&Bs[k][tx * 8];
            float4 b1 = *(const float4*)&Bs[k][tx * 8 + 4];
            float av[8] = {a0.x, a0.y, a0.z, a0.w, a1.x, a1.y, a1.z, a1.w};
            float bv[8] = {b0.x, b0.y, b0.z, b0.w, b1.x, b1.y, b1.z, b1.w};
#pragma unroll
            for (int i = 0; i < 8; i++)
#pragma unroll
                for (int j = 0; j < 8; j++)
                    acc[i][j] += av[i] * bv[j];
        }
        __syncthreads();
    }
#pragma unroll
    for (int i = 0; i < 8; i++) {
        float* yp = Y + (bm + ty * 8 + i) * ED + bn + tx * 8;
        *(float4*)(yp)     = make_float4(acc[i][0], acc[i][1], acc[i][2], acc[i][3]);
        *(float4*)(yp + 4) = make_float4(acc[i][4], acc[i][5], acc[i][6], acc[i][7]);
    }
}

// ---------------------------------------------------------------------------
// QK^T GEMM + exp2 epilogue -> P (fp16).  S[r][c] = sum_e vq[r][e]*ok[c][e]
// ---------------------------------------------------------------------------
__global__ __launch_bounds__(256, 2) void qk_kernel()
{
    __half* P = (__half*)g_P4;
    __shared__ float As[16][132];
    __shared__ float Bs[16][132];
    int bm = blockIdx.x * 128;
    int bn = blockIdx.y * 128;
    int tid = threadIdx.x;
    int ty = tid >> 4, tx = tid & 15;

    float acc[8][8];
#pragma unroll
    for (int i = 0; i < 8; i++)
#pragma unroll
        for (int j = 0; j < 8; j++) acc[i][j] = 0.f;

    for (int k0 = 0; k0 < ED; k0 += 16) {
#pragma unroll
        for (int it = 0; it < 2; it++) {
            int idx = tid + it * 256;
            int row = idx & 127;
            int k4  = (idx >> 7) << 2;
            float4 a = *(const float4*)(g_vq + (bm + row) * ED + k0 + k4);
            As[k4 + 0][row] = a.x; As[k4 + 1][row] = a.y;
            As[k4 + 2][row] = a.z; As[k4 + 3][row] = a.w;
            float4 b = *(const float4*)(g_ok + (bn + row) * ED + k0 + k4);
            Bs[k4 + 0][row] = b.x; Bs[k4 + 1][row] = b.y;
            Bs[k4 + 2][row] = b.z; Bs[k4 + 3][row] = b.w;
        }
        __syncthreads();
#pragma unroll
        for (int k = 0; k < 16; k++) {
            float4 a0 = *(const float4*)&As[k][ty * 8];
            float4 a1 = *(const float4*)&As[k][ty * 8 + 4];
            float4 b0 = *(const float4*)&Bs[k][tx * 8];
            float4 b1 = *(const float4*)&Bs[k][tx * 8 + 4];
            float av[8] = {a0.x, a0.y, a0.z, a0.w, a1.x, a1.y, a1.z, a1.w};
            float bv[8] = {b0.x, b0.y, b0.z, b0.w, b1.x, b1.y, b1.z, b1.w};
#pragma unroll
            for (int i = 0; i < 8; i++)
#pragma unroll
                for (int j = 0; j < 8; j++)
                    acc[i][j] += av[i] * bv[j];
        }
        __syncthreads();
    }
    // epilogue: p = exp2(s * scale), store fp16 (fixed softmax max = 0)
#pragma unroll
    for (int i = 0; i < 8; i++) {
        __half hv[8];
#pragma unroll
        for (int j = 0; j < 8; j++)
            hv[j] = __float2half_rn(exp2f(acc[i][j] * SM_SCALE));
        *(uint4*)(P + (size_t)(bm + ty * 8 + i) * NM + bn + tx * 8) = *(uint4*)hv;
    }
}

// ---------------------------------------------------------------------------
// PV GEMM: O[r][e] = sum_kv P[r][kv] * ov[kv][e].  A fp16, B fp32 natural.
// ---------------------------------------------------------------------------
__global__ __launch_bounds__(256, 2) void pv_kernel()
{
    const __half* P = (const __half*)g_P4;
    __shared__ float As[16][132];
    __shared__ float Bs[16][132];
    int bm = blockIdx.x * 128;
    int bn = blockIdx.y * 128;
    int tid = threadIdx.x;
    int ty = tid >> 4, tx = tid & 15;

    float acc[8][8];
#pragma unroll
    for (int i = 0; i < 8; i++)
#pragma unroll
        for (int j = 0; j < 8; j++) acc[i][j] = 0.f;

    int arow = tid & 127;
    int ak8  = (tid >> 7) << 3;

    for (int k0 = 0; k0 < NM; k0 += 16) {
        // A: 8 fp16 per thread, convert + transpose-store (k-major)
        uint4 araw = *(const uint4*)(P + (size_t)(bm + arow) * NM + k0 + ak8);
        const __half2* h2 = (const __half2*)&araw;
#pragma unroll
        for (int j = 0; j < 4; j++) {
            float2 f = __half22float2(h2[j]);
            As[ak8 + 2 * j + 0][arow] = f.x;
            As[ak8 + 2 * j + 1][arow] = f.y;
        }
        // B: V tile natural layout, 2 float4 per thread
#pragma unroll
        for (int it = 0; it < 2; it++) {
            int idx = tid + it * 256;
            int kk  = idx >> 5;
            int c4  = (idx & 31) << 2;
            *(float4*)&Bs[kk][c4] = *(const float4*)(g_ov + (k0 + kk) * ED + bn + c4);
        }
        __syncthreads();
#pragma unroll
        for (int k = 0; k < 16; k++) {
            float4 a0 = *(const float4*)&As[k][ty * 8];
            float4 a1 = *(const float4*)&As[k][ty * 8 + 4];
            float4 b0 = *(const float4*)&Bs[k][tx * 8];
            float4 b1 = *(const float4*)&Bs[k][tx * 8 + 4];
            float av[8] = {a0.x, a0.y, a0.z, a0.w, a1.x, a1.y, a1.z, a1.w};
            float bv[8] = {b0.x, b0.y, b0.z, b0.w, b1.x, b1.y, b1.z, b1.w};
#pragma unroll
            for (int i = 0; i < 8; i++)
#pragma unroll
                for (int j = 0; j < 8; j++)
                    acc[i][j] += av[i] * bv[j];
        }
        __syncthreads();
    }
#pragma unroll
    for (int i = 0; i < 8; i++) {
        float* yp = g_O + (bm + ty * 8 + i) * ED + bn + tx * 8;
        *(float4*)(yp)     = make_float4(acc[i][0], acc[i][1], acc[i][2], acc[i][3]);
        *(float4*)(yp + 4) = make_float4(acc[i][4], acc[i][5], acc[i][6], acc[i][7]);
    }
}

// ---------------------------------------------------------------------------
// Epilogue: row-sum of P (deterministic), self term, normalize, residual, LN.
// One warp per row, 8 rows per block.
// ---------------------------------------------------------------------------
__global__ __launch_bounds__(256) void epi_kernel(
    const float* __restrict__ v_code,
    const float* __restrict__ gamma,
    const float* __restrict__ beta,
    float* __restrict__ out)
{
    int warp = threadIdx.x >> 5, lane = threadIdx.x & 31;
    int r = blockIdx.x * 8 + warp;

    // sum of P row (fp16 numerators)
    const __half2* Pr = (const __half2*)((const __half*)g_P4 + (size_t)r * NM);
    float s = 0.f;
#pragma unroll
    for (int t = 0; t < 64; t++) {
        float2 f = __half22float2(Pr[lane + 32 * t]);
        s += f.x + f.y;
    }
#pragma unroll
    for (int o = 16; o > 0; o >>= 1) s += __shfl_xor_sync(0xffffffffu, s, o);

    // self-attention term
    const float* q  = g_vq + r * ED;
    const float* kk = g_vk + r * ED;
    float sd = 0.f;
#pragma unroll
    for (int t = 0; t < 16; t++) { int e = lane + 32 * t; sd += q[e] * kk[e]; }
#pragma unroll
    for (int o = 16; o > 0; o >>= 1) sd += __shfl_xor_sync(0xffffffffu, sd, o);
    float pself = exp2f(sd * SM_SCALE);
    float linv = 1.f / (s + pself);

    const float* vv = g_vv + r * ED;
    const float* vc = v_code + r * ED;
    const float* Or = g_O + r * ED;

    float vals[16];
    float mu = 0.f;
#pragma unroll
    for (int t = 0; t < 16; t++) {
        int e = lane + 32 * t;
        float v = (Or[e] + pself * vv[e]) * linv + vc[e];
        vals[t] = v; mu += v;
    }
#pragma unroll
    for (int o = 16; o > 0; o >>= 1) mu += __shfl_xor_sync(0xffffffffu, mu, o);
    mu *= (1.f / 512.f);
    float var = 0.f;
#pragma unroll
    for (int t = 0; t < 16; t++) { float d = vals[t] - mu; var += d * d; }
#pragma unroll
    for (int o = 16; o > 0; o >>= 1) var += __shfl_xor_sync(0xffffffffu, var, o);
    float rstd = rsqrtf(var * (1.f / 512.f) + 1e-6f);
#pragma unroll
    for (int t = 0; t < 16; t++) {
        int e = lane + 32 * t;
        out[r * ED + e] = (vals[t] - mu) * rstd * gamma[e] + beta[e];
    }
}

// ---------------------------------------------------------------------------
extern "C" void kernel_launch(void* const* d_in, const int* in_sizes, int n_in,
                              void* d_out, int out_size)
{
    const float* v_code   = (const float*)d_in[0];
    const float* obs_code = (const float*)d_in[1];
    const float* Wq       = (const float*)d_in[2];
    const float* Wk       = (const float*)d_in[3];
    const float* Wv       = (const float*)d_in[4];
    const float* gamma    = (const float*)d_in[5];
    const float* beta     = (const float*)d_in[6];
    float* out = (float*)d_out;

    float *vq, *vk, *vv, *ok, *ov;
    cudaGetSymbolAddress((void**)&vq, g_vq);
    cudaGetSymbolAddress((void**)&vk, g_vk);
    cudaGetSymbolAddress((void**)&vv, g_vv);
    cudaGetSymbolAddress((void**)&ok, g_ok);
    cudaGetSymbolAddress((void**)&ov, g_ov);

    dim3 blk(256);
    proj_kernel<<<dim3(NQ / 128, ED / 128), blk>>>(v_code, Wq, vq);
    proj_kernel<<<dim3(NQ / 128, ED / 128), blk>>>(v_code, Wk, vk);
    proj_kernel<<<dim3(NQ / 128, ED / 128), blk>>>(v_code, Wv, vv);
    proj_kernel<<<dim3(NM / 128, ED / 128), blk>>>(obs_code, Wk, ok);
    proj_kernel<<<dim3(NM / 128, ED / 128), blk>>>(obs_code, Wv, ov);

    qk_kernel<<<dim3(NQ / 128, NM / 128), blk>>>();
    pv_kernel<<<dim3(NQ / 128, ED / 128), blk>>>();
    epi_kernel<<<NQ / 8, blk>>>(v_code, gamma, beta, out);
}

// round 4
// speedup vs baseline: 10.3653x; 6.6352x over previous
#include <cuda_runtime.h>
#include <cuda_bf16.h>
#include <cstdint>

#define NQ 8192
#define NM 4096
#define ED 512
// log2(e) / TEMPERATURE  (TEMPERATURE = sqrt(512))
#define SM_SCALE (1.4426950408889634f / 22.627416997969522f)

// ---------------- scratch (__device__ globals; no allocs allowed) ----------
__device__ __nv_bfloat16 g_vc16[NQ * ED];
__device__ __nv_bfloat16 g_oc16[NM * ED];
__device__ __nv_bfloat16 g_wq16[ED * ED];
__device__ __nv_bfloat16 g_wk16[ED * ED];
__device__ __nv_bfloat16 g_wv16[ED * ED];
__device__ __nv_bfloat16 g_vq16[NQ * ED];
__device__ __nv_bfloat16 g_vk16[NQ * ED];
__device__ __nv_bfloat16 g_vv16[NQ * ED];
__device__ __nv_bfloat16 g_ok16[NM * ED];
__device__ __nv_bfloat16 g_ovT[(size_t)ED * NM];   // transposed V-proj of obs
__device__ __nv_bfloat16 g_P[(size_t)NQ * NM];     // softmax numerators
__device__ float g_O[NQ * ED];

// ---------------- helpers --------------------------------------------------
__device__ __forceinline__ uint32_t smem_u32(const void* p) {
    uint32_t a;
    asm("{ .reg .u64 t; cvta.to.shared.u64 t, %1; cvt.u32.u64 %0, t; }" : "=r"(a) : "l"(p));
    return a;
}

#define LDM4(r, addr) \
    asm volatile("ldmatrix.sync.aligned.m8n8.x4.shared.b16 {%0,%1,%2,%3}, [%4];" \
        : "=r"((r)[0]), "=r"((r)[1]), "=r"((r)[2]), "=r"((r)[3]) : "r"(addr))

#define MMA16816(d, a, b0, b1) \
    asm volatile("mma.sync.aligned.m16n8k16.row.col.f32.bf16.bf16.f32 " \
        "{%0,%1,%2,%3}, {%4,%5,%6,%7}, {%8,%9}, {%0,%1,%2,%3};" \
        : "+f"((d)[0]), "+f"((d)[1]), "+f"((d)[2]), "+f"((d)[3]) \
        : "r"((a)[0]), "r"((a)[1]), "r"((a)[2]), "r"((a)[3]), "r"(b0), "r"(b1))

// load one 128x64 bf16 tile pair (A,B) into SW128-swizzled smem via cp.async
__device__ __forceinline__ void load_tiles(uint32_t ab, uint32_t bb,
    const __nv_bfloat16* __restrict__ Ag, int lda,
    const __nv_bfloat16* __restrict__ Bg, int ldb, int tid)
{
    int c  = tid & 7;
    int r0 = tid >> 3;
#pragma unroll
    for (int it = 0; it < 4; it++) {
        int row = r0 + it * 32;
        uint32_t off = (uint32_t)(row * 128 + (((c << 4)) ^ ((row & 7) << 4)));
        asm volatile("cp.async.cg.shared.global [%0], [%1], 16;"
            :: "r"(ab + off), "l"(Ag + (size_t)row * lda + c * 8) : "memory");
        asm volatile("cp.async.cg.shared.global [%0], [%1], 16;"
            :: "r"(bb + off), "l"(Bg + (size_t)row * ldb + c * 8) : "memory");
    }
    asm volatile("cp.async.commit_group;" ::: "memory");
}

// ---------------------------------------------------------------------------
// fp32 -> bf16 elementwise convert
// ---------------------------------------------------------------------------
__global__ __launch_bounds__(256) void cvt_kernel(
    const float4* __restrict__ src, uint2* __restrict__ dst, int n4)
{
    int i = blockIdx.x * 256 + threadIdx.x;
    if (i < n4) {
        float4 v = src[i];
        __nv_bfloat162 a = __floats2bfloat162_rn(v.x, v.y);
        __nv_bfloat162 b = __floats2bfloat162_rn(v.z, v.w);
        uint2 o;
        o.x = *(uint32_t*)&a;
        o.y = *(uint32_t*)&b;
        dst[i] = o;
    }
}

// ---------------------------------------------------------------------------
// bf16 GEMM via mma.sync: D[128,128] = A[128,K] @ B[128,K]^T per CTA.
// 256 threads, warp grid 2(M) x 4(N), warp tile 64x32, BK=64, double buffered.
// mode 0: store bf16 row-major   mode 1: exp2(x*SM_SCALE) -> bf16 row-major
// mode 2: store fp32 row-major   mode 3: store bf16 transposed C[n*ldc+m]
// ---------------------------------------------------------------------------
__global__ __launch_bounds__(256) void gemm_mma(
    const __nv_bfloat16* __restrict__ A, int lda,
    const __nv_bfloat16* __restrict__ B, int ldb,
    void* __restrict__ C, int ldc, int K, int mode)
{
    extern __shared__ char smem_raw[];
    uint32_t sb = smem_u32(smem_raw);

    const int tid = threadIdx.x;
    const int lane = tid & 31, wid = tid >> 5;
    const int wm = wid >> 2, wn = wid & 3;       // warp grid 2x4
    const int bm = blockIdx.x * 128, bn = blockIdx.y * 128;
    const int nc = K >> 6;

    const __nv_bfloat16* Abase = A + (size_t)bm * lda;
    const __nv_bfloat16* Bbase = B + (size_t)bn * ldb;

    load_tiles(sb, sb + 16384, Abase, lda, Bbase, ldb, tid);
    if (nc > 1)
        load_tiles(sb + 32768, sb + 49152, Abase + 64, lda, Bbase + 64, ldb, tid);

    float acc[4][4][4];
#pragma unroll
    for (int i = 0; i < 4; i++)
#pragma unroll
        for (int j = 0; j < 4; j++)
#pragma unroll
            for (int k = 0; k < 4; k++) acc[i][j][k] = 0.f;

    // per-lane ldmatrix row bases + swizzle patterns
    uint32_t a_rb[4], a_p[4], b_rb[2], b_p[2];
#pragma unroll
    for (int mi = 0; mi < 4; mi++) {
        int row = wm * 64 + mi * 16 + (lane & 15);
        a_rb[mi] = (uint32_t)(row * 128);
        a_p[mi]  = (uint32_t)((row & 7) << 4);
    }
#pragma unroll
    for (int nb = 0; nb < 2; nb++) {
        int row = wn * 32 + nb * 16 + (lane & 15);
        b_rb[nb] = (uint32_t)(row * 128);
        b_p[nb]  = (uint32_t)((row & 7) << 4);
    }
    const uint32_t h16 = (uint32_t)((lane >> 4) << 4);

    for (int i = 0; i < nc; i++) {
        int s = i & 1;
        if (i + 1 < nc) asm volatile("cp.async.wait_group 1;" ::: "memory");
        else            asm volatile("cp.async.wait_group 0;" ::: "memory");
        __syncthreads();

        uint32_t ab = sb + s * 32768;
        uint32_t bb = ab + 16384;
#pragma unroll
        for (int ks = 0; ks < 4; ks++) {
            uint32_t kh = (uint32_t)(ks << 5) | h16;
            uint32_t af[4][4], bf[2][4];
#pragma unroll
            for (int mi = 0; mi < 4; mi++)
                LDM4(af[mi], ab + a_rb[mi] + (kh ^ a_p[mi]));
#pragma unroll
            for (int nb = 0; nb < 2; nb++)
                LDM4(bf[nb], bb + b_rb[nb] + (kh ^ b_p[nb]));
#pragma unroll
            for (int mi = 0; mi < 4; mi++) {
#pragma unroll
                for (int nb = 0; nb < 2; nb++) {
                    MMA16816(acc[mi][nb * 2 + 0], af[mi], bf[nb][0], bf[nb][2]);
                    MMA16816(acc[mi][nb * 2 + 1], af[mi], bf[nb][1], bf[nb][3]);
                }
            }
        }
        __syncthreads();
        if (i + 2 < nc)
            load_tiles(ab, bb, Abase + (i + 2) * 64, lda, Bbase + (i + 2) * 64, ldb, tid);
    }

    // ---- epilogue straight from registers ---------------------------------
    const int g = lane >> 2, tg = lane & 3;
#pragma unroll
    for (int mi = 0; mi < 4; mi++) {
#pragma unroll
        for (int nj = 0; nj < 4; nj++) {
            float* c = acc[mi][nj];
            int m0 = bm + wm * 64 + mi * 16 + g;
            int n0 = bn + wn * 32 + nj * 8 + tg * 2;
            if (mode == 2) {
                float* Cf = (float*)C;
                *(float2*)(Cf + (size_t)m0 * ldc + n0)       = make_float2(c[0], c[1]);
                *(float2*)(Cf + (size_t)(m0 + 8) * ldc + n0) = make_float2(c[2], c[3]);
            } else if (mode == 3) {
                __nv_bfloat16* Cb = (__nv_bfloat16*)C;
                Cb[(size_t)n0 * ldc + m0]           = __float2bfloat16_rn(c[0]);
                Cb[(size_t)(n0 + 1) * ldc + m0]     = __float2bfloat16_rn(c[1]);
                Cb[(size_t)n0 * ldc + m0 + 8]       = __float2bfloat16_rn(c[2]);
                Cb[(size_t)(n0 + 1) * ldc + m0 + 8] = __float2bfloat16_rn(c[3]);
            } else {
                __nv_bfloat16* Cb = (__nv_bfloat16*)C;
                float v0 = c[0], v1 = c[1], v2 = c[2], v3 = c[3];
                if (mode == 1) {
                    v0 = exp2f(v0 * SM_SCALE); v1 = exp2f(v1 * SM_SCALE);
                    v2 = exp2f(v2 * SM_SCALE); v3 = exp2f(v3 * SM_SCALE);
                }
                __nv_bfloat162 p0 = __floats2bfloat162_rn(v0, v1);
                __nv_bfloat162 p1 = __floats2bfloat162_rn(v2, v3);
                *(uint32_t*)(Cb + (size_t)m0 * ldc + n0)       = *(uint32_t*)&p0;
                *(uint32_t*)(Cb + (size_t)(m0 + 8) * ldc + n0) = *(uint32_t*)&p1;
            }
        }
    }
}

// ---------------------------------------------------------------------------
// Epilogue: row-sum of P, self term, normalize, residual, layernorm.
// One warp per row.
// ---------------------------------------------------------------------------
__global__ __launch_bounds__(256) void epi_kernel(
    const float* __restrict__ v_code,
    const float* __restrict__ gamma,
    const float* __restrict__ beta,
    float* __restrict__ out)
{
    int warp = threadIdx.x >> 5, lane = threadIdx.x & 31;
    int r = blockIdx.x * 8 + warp;

    // sum of P row (bf16 numerators)
    const uint4* Pr = (const uint4*)(g_P + (size_t)r * NM);
    float s = 0.f;
#pragma unroll
    for (int t = 0; t < 16; t++) {
        uint4 u = Pr[lane + 32 * t];
        float2 f0 = __bfloat1622float2(*(__nv_bfloat162*)&u.x);
        float2 f1 = __bfloat1622float2(*(__nv_bfloat162*)&u.y);
        float2 f2 = __bfloat1622float2(*(__nv_bfloat162*)&u.z);
        float2 f3 = __bfloat1622float2(*(__nv_bfloat162*)&u.w);
        s += (f0.x + f0.y) + (f1.x + f1.y) + (f2.x + f2.y) + (f3.x + f3.y);
    }
#pragma unroll
    for (int o = 16; o > 0; o >>= 1) s += __shfl_xor_sync(0xffffffffu, s, o);

    // self-attention score q . k (bf16 operands)
    const uint4* q4 = (const uint4*)(g_vq16 + (size_t)r * ED);
    const uint4* k4 = (const uint4*)(g_vk16 + (size_t)r * ED);
    float sd = 0.f;
#pragma unroll
    for (int t = 0; t < 2; t++) {
        uint4 uq = q4[lane + 32 * t], uk = k4[lane + 32 * t];
        const __nv_bfloat162* hq = (const __nv_bfloat162*)&uq;
        const __nv_bfloat162* hk = (const __nv_bfloat162*)&uk;
#pragma unroll
        for (int j = 0; j < 4; j++) {
            float2 a = __bfloat1622float2(hq[j]);
            float2 b = __bfloat1622float2(hk[j]);
            sd += a.x * b.x + a.y * b.y;
        }
    }
#pragma unroll
    for (int o = 16; o > 0; o >>= 1) sd += __shfl_xor_sync(0xffffffffu, sd, o);
    float pself = exp2f(sd * SM_SCALE);
    float linv = 1.f / (s + pself);

    const float* vc = v_code + (size_t)r * ED;
    const float* Or = g_O + (size_t)r * ED;
    const __nv_bfloat16* vv = g_vv16 + (size_t)r * ED;

    float vals[16];
    float mu = 0.f;
#pragma unroll
    for (int t = 0; t < 16; t++) {
        int e = lane + 32 * t;
        float v = (Or[e] + pself * __bfloat162float(vv[e])) * linv + vc[e];
        vals[t] = v; mu += v;
    }
#pragma unroll
    for (int o = 16; o > 0; o >>= 1) mu += __shfl_xor_sync(0xffffffffu, mu, o);
    mu *= (1.f / 512.f);
    float var = 0.f;
#pragma unroll
    for (int t = 0; t < 16; t++) { float d = vals[t] - mu; var += d * d; }
#pragma unroll
    for (int o = 16; o > 0; o >>= 1) var += __shfl_xor_sync(0xffffffffu, var, o);
    float rstd = rsqrtf(var * (1.f / 512.f) + 1e-6f);
#pragma unroll
    for (int t = 0; t < 16; t++) {
        int e = lane + 32 * t;
        out[(size_t)r * ED + e] = (vals[t] - mu) * rstd * gamma[e] + beta[e];
    }
}

// ---------------------------------------------------------------------------
extern "C" void kernel_launch(void* const* d_in, const int* in_sizes, int n_in,
                              void* d_out, int out_size)
{
    const float* v_code   = (const float*)d_in[0];
    const float* obs_code = (const float*)d_in[1];
    const float* Wq       = (const float*)d_in[2];
    const float* Wk       = (const float*)d_in[3];
    const float* Wv       = (const float*)d_in[4];
    const float* gamma    = (const float*)d_in[5];
    const float* beta     = (const float*)d_in[6];
    float* out = (float*)d_out;

    __nv_bfloat16 *vc16, *oc16, *wq16, *wk16, *wv16, *vq16, *vk16, *vv16, *ok16, *ovT, *P;
    float* O;
    cudaGetSymbolAddress((void**)&vc16, g_vc16);
    cudaGetSymbolAddress((void**)&oc16, g_oc16);
    cudaGetSymbolAddress((void**)&wq16, g_wq16);
    cudaGetSymbolAddress((void**)&wk16, g_wk16);
    cudaGetSymbolAddress((void**)&wv16, g_wv16);
    cudaGetSymbolAddress((void**)&vq16, g_vq16);
    cudaGetSymbolAddress((void**)&vk16, g_vk16);
    cudaGetSymbolAddress((void**)&vv16, g_vv16);
    cudaGetSymbolAddress((void**)&ok16, g_ok16);
    cudaGetSymbolAddress((void**)&ovT,  g_ovT);
    cudaGetSymbolAddress((void**)&P,    g_P);
    cudaGetSymbolAddress((void**)&O,    g_O);

    // fp32 -> bf16 converts
    cvt_kernel<<<(NQ * ED / 4 + 255) / 256, 256>>>((const float4*)v_code,   (uint2*)vc16, NQ * ED / 4);
    cvt_kernel<<<(NM * ED / 4 + 255) / 256, 256>>>((const float4*)obs_code, (uint2*)oc16, NM * ED / 4);
    cvt_kernel<<<(ED * ED / 4 + 255) / 256, 256>>>((const float4*)Wq, (uint2*)wq16, ED * ED / 4);
    cvt_kernel<<<(ED * ED / 4 + 255) / 256, 256>>>((const float4*)Wk, (uint2*)wk16, ED * ED / 4);
    cvt_kernel<<<(ED * ED / 4 + 255) / 256, 256>>>((const float4*)Wv, (uint2*)wv16, ED * ED / 4);

    const int smem = 65536;
    cudaFuncSetAttribute(gemm_mma, cudaFuncAttributeMaxDynamicSharedMemorySize, smem);
    dim3 blk(256);

    // projections (bf16 outputs)
    gemm_mma<<<dim3(NQ / 128, ED / 128), blk, smem>>>(vc16, ED, wq16, ED, vq16, ED, ED, 0);
    gemm_mma<<<dim3(NQ / 128, ED / 128), blk, smem>>>(vc16, ED, wk16, ED, vk16, ED, ED, 0);
    gemm_mma<<<dim3(NQ / 128, ED / 128), blk, smem>>>(vc16, ED, wv16, ED, vv16, ED, ED, 0);
    gemm_mma<<<dim3(NM / 128, ED / 128), blk, smem>>>(oc16, ED, wk16, ED, ok16, ED, ED, 0);
    gemm_mma<<<dim3(NM / 128, ED / 128), blk, smem>>>(oc16, ED, wv16, ED, ovT, NM, ED, 3);

    // QK^T with fused exp2 -> P (bf16)
    gemm_mma<<<dim3(NQ / 128, NM / 128), blk, smem>>>(vq16, ED, ok16, ED, P, NM, ED, 1);

    // P @ ovT^T -> O (fp32)
    gemm_mma<<<dim3(NQ / 128, ED / 128), blk, smem>>>(P, NM, ovT, NM, O, ED, NM, 2);

    epi_kernel<<<NQ / 8, blk>>>(v_code, gamma, beta, out);
}

// round 5
// speedup vs baseline: 11.3366x; 1.0937x over previous
#include <cuda_runtime.h>
#include <cuda_fp16.h>
#include <cstdint>

#define NQ 8192
#define NM 4096
#define ED 512
// log2(e) / TEMPERATURE  (TEMPERATURE = sqrt(512))
#define SM_SCALE (1.4426950408889634f / 22.627416997969522f)

// ---------------- scratch (__device__ globals; no allocs allowed) ----------
__device__ __half g_vch[NQ * ED];
__device__ __half g_och[NM * ED];
__device__ __half g_wqh[ED * ED];
__device__ __half g_wkh[ED * ED];
__device__ __half g_wvh[ED * ED];
__device__ __half g_vqh[NQ * ED];
__device__ __half g_vkh[NQ * ED];
__device__ __half g_vvh[NQ * ED];
__device__ __half g_okh[NM * ED];
__device__ __half g_ovT[(size_t)ED * NM];   // transposed V-proj of obs
__device__ __half g_P[(size_t)NQ * NM];     // softmax numerators (fp16)
__device__ float g_Opart[4][NQ * ED];       // split-K partials of O

// ---------------- helpers --------------------------------------------------
__device__ __forceinline__ uint32_t smem_u32(const void* p) {
    uint32_t a;
    asm("{ .reg .u64 t; cvta.to.shared.u64 t, %1; cvt.u32.u64 %0, t; }" : "=r"(a) : "l"(p));
    return a;
}

#define LDM4(r, addr) \
    asm volatile("ldmatrix.sync.aligned.m8n8.x4.shared.b16 {%0,%1,%2,%3}, [%4];" \
        : "=r"((r)[0]), "=r"((r)[1]), "=r"((r)[2]), "=r"((r)[3]) : "r"(addr))

// fp16 accumulate MMA: D(f16x2 pair) += A(f16) * B(f16)
#define MMAH(d, a, b0, b1) \
    asm volatile("mma.sync.aligned.m16n8k16.row.col.f16.f16.f16.f16 " \
        "{%0,%1}, {%2,%3,%4,%5}, {%6,%7}, {%0,%1};" \
        : "+r"((d)[0]), "+r"((d)[1]) \
        : "r"((a)[0]), "r"((a)[1]), "r"((a)[2]), "r"((a)[3]), "r"(b0), "r"(b1))

// fast exp2 on the FMA/ALU pipes (cubic, |rel err| < 5e-4)
__device__ __forceinline__ float fast_exp2(float x) {
    float t = x + 12582912.f;                 // round-to-nearest-int trick
    float fl = t - 12582912.f;
    float f = x - fl;                         // f in [-0.5, 0.5]
    int n = __float_as_int(t) - 0x4B400000;   // signed integer part
    float p = fmaf(fmaf(fmaf(0.0555041086f, f, 0.2402265069f), f, 0.6931471806f), f, 1.0004f * 1.0f);
    return __int_as_float(__float_as_int(p) + (n << 23));
}

// load one 128x64 fp16 tile pair (A,B) into SW128-swizzled smem via cp.async
__device__ __forceinline__ void load_tiles_h(uint32_t ab, uint32_t bb,
    const __half* __restrict__ Ag, int lda,
    const __half* __restrict__ Bg, int ldb, int tid)
{
    int c  = tid & 7;
    int r0 = tid >> 3;
#pragma unroll
    for (int it = 0; it < 4; it++) {
        int row = r0 + it * 32;
        uint32_t off = (uint32_t)(row * 128 + ((c << 4) ^ ((row & 7) << 4)));
        asm volatile("cp.async.cg.shared.global [%0], [%1], 16;"
            :: "r"(ab + off), "l"(Ag + (size_t)row * lda + c * 8) : "memory");
        asm volatile("cp.async.cg.shared.global [%0], [%1], 16;"
            :: "r"(bb + off), "l"(Bg + (size_t)row * ldb + c * 8) : "memory");
    }
    asm volatile("cp.async.commit_group;" ::: "memory");
}

// ---------------------------------------------------------------------------
// fp32 -> fp16 conversion of all inputs in ONE launch
// ---------------------------------------------------------------------------
__global__ __launch_bounds__(256) void cvt_all(
    const float4* __restrict__ vc, const float4* __restrict__ oc,
    const float4* __restrict__ wq, const float4* __restrict__ wk,
    const float4* __restrict__ wv)
{
    const int n_vc = NQ * ED / 4, n_oc = NM * ED / 4, n_w = ED * ED / 4;
    int i = blockIdx.x * 256 + threadIdx.x;
    const float4* s; uint2* d; int j;
    if (i < n_vc)                      { s = vc; d = (uint2*)g_vch; j = i; }
    else if (i < n_vc + n_oc)          { s = oc; d = (uint2*)g_och; j = i - n_vc; }
    else if (i < n_vc + n_oc + n_w)    { s = wq; d = (uint2*)g_wqh; j = i - n_vc - n_oc; }
    else if (i < n_vc + n_oc + 2*n_w)  { s = wk; d = (uint2*)g_wkh; j = i - n_vc - n_oc - n_w; }
    else if (i < n_vc + n_oc + 3*n_w)  { s = wv; d = (uint2*)g_wvh; j = i - n_vc - n_oc - 2*n_w; }
    else return;
    float4 v = s[j];
    __half2 a = __floats2half2_rn(v.x, v.y);
    __half2 b = __floats2half2_rn(v.z, v.w);
    d[j] = make_uint2(*(uint32_t*)&a, *(uint32_t*)&b);
}

// ---------------------------------------------------------------------------
// fp16 GEMM via mma.sync (f16 accumulate): D[128,128] = A[128,K] @ B[128,K]^T.
// 256 threads, warp grid 2x4, warp tile 64x32, BK=64, double buffered.
// mode 0: store fp16 row-major    mode 1: exp2(x*SM_SCALE) -> fp16 row-major
// mode 2: store fp32 row-major    mode 3: store fp16 transposed C[n*ldc+m]
// nsy: #n-tiles in gridDim.y; blocks beyond that are split-K slices.
// ---------------------------------------------------------------------------
__global__ __launch_bounds__(256) void gemm_h(
    const __half* __restrict__ A, int lda,
    const __half* __restrict__ B, int ldb,
    void* __restrict__ C, int ldc, int K, int mode, int nsy)
{
    extern __shared__ char smem_raw[];
    uint32_t sb = smem_u32(smem_raw);

    const int tid = threadIdx.x;
    const int lane = tid & 31, wid = tid >> 5;
    const int wm = wid >> 2, wn = wid & 3;       // warp grid 2x4
    const int split = blockIdx.y / nsy;
    const int bm = blockIdx.x * 128, bn = (blockIdx.y % nsy) * 128;
    const int nc = K >> 6;

    A += (size_t)split * K;                      // split-K column offset
    B += (size_t)split * K;
    float* Csplit = (float*)C + (size_t)split * ((size_t)gridDim.x * 128) * ldc;

    const __half* Abase = A + (size_t)bm * lda;
    const __half* Bbase = B + (size_t)bn * ldb;

    load_tiles_h(sb, sb + 16384, Abase, lda, Bbase, ldb, tid);
    if (nc > 1)
        load_tiles_h(sb + 32768, sb + 49152, Abase + 64, lda, Bbase + 64, ldb, tid);

    uint32_t acc[4][4][2];
#pragma unroll
    for (int i = 0; i < 4; i++)
#pragma unroll
        for (int j = 0; j < 4; j++) { acc[i][j][0] = 0u; acc[i][j][1] = 0u; }

    // per-lane ldmatrix row bases + swizzle patterns
    uint32_t a_rb[4], a_p[4], b_rb[2], b_p[2];
#pragma unroll
    for (int mi = 0; mi < 4; mi++) {
        int row = wm * 64 + mi * 16 + (lane & 15);
        a_rb[mi] = (uint32_t)(row * 128);
        a_p[mi]  = (uint32_t)((row & 7) << 4);
    }
#pragma unroll
    for (int nb = 0; nb < 2; nb++) {
        int row = wn * 32 + nb * 16 + (lane & 15);
        b_rb[nb] = (uint32_t)(row * 128);
        b_p[nb]  = (uint32_t)((row & 7) << 4);
    }
    const uint32_t h16 = (uint32_t)((lane >> 4) << 4);

    for (int i = 0; i < nc; i++) {
        int s = i & 1;
        if (i + 1 < nc) asm volatile("cp.async.wait_group 1;" ::: "memory");
        else            asm volatile("cp.async.wait_group 0;" ::: "memory");
        __syncthreads();

        uint32_t ab = sb + s * 32768;
        uint32_t bb = ab + 16384;
#pragma unroll
        for (int ks = 0; ks < 4; ks++) {
            uint32_t kh = (uint32_t)(ks << 5) | h16;
            uint32_t af[4][4], bf[2][4];
#pragma unroll
            for (int mi = 0; mi < 4; mi++)
                LDM4(af[mi], ab + a_rb[mi] + (kh ^ a_p[mi]));
#pragma unroll
            for (int nb = 0; nb < 2; nb++)
                LDM4(bf[nb], bb + b_rb[nb] + (kh ^ b_p[nb]));
#pragma unroll
            for (int mi = 0; mi < 4; mi++) {
#pragma unroll
                for (int nb = 0; nb < 2; nb++) {
                    MMAH(acc[mi][nb * 2 + 0], af[mi], bf[nb][0], bf[nb][2]);
                    MMAH(acc[mi][nb * 2 + 1], af[mi], bf[nb][1], bf[nb][3]);
                }
            }
        }
        __syncthreads();
        if (i + 2 < nc)
            load_tiles_h(ab, bb, Abase + (i + 2) * 64, lda, Bbase + (i + 2) * 64, ldb, tid);
    }

    // ---- epilogue straight from registers ---------------------------------
    const int g = lane >> 2, tg = lane & 3;
#pragma unroll
    for (int mi = 0; mi < 4; mi++) {
#pragma unroll
        for (int nj = 0; nj < 4; nj++) {
            int m0 = bm + wm * 64 + mi * 16 + g;
            int n0 = bn + wn * 32 + nj * 8 + tg * 2;
            if (mode == 0) {
                __half* Ch = (__half*)C;
                *(uint32_t*)(Ch + (size_t)m0 * ldc + n0)       = acc[mi][nj][0];
                *(uint32_t*)(Ch + (size_t)(m0 + 8) * ldc + n0) = acc[mi][nj][1];
            } else if (mode == 1) {
                __half* Ch = (__half*)C;
                float2 lo = __half22float2(*(__half2*)&acc[mi][nj][0]);
                float2 hi = __half22float2(*(__half2*)&acc[mi][nj][1]);
                float p0, p1, p2, p3;
                if (nj & 1) {      // FFMA-pipe polynomial path
                    p0 = fast_exp2(lo.x * SM_SCALE); p1 = fast_exp2(lo.y * SM_SCALE);
                    p2 = fast_exp2(hi.x * SM_SCALE); p3 = fast_exp2(hi.y * SM_SCALE);
                } else {           // MUFU path
                    p0 = exp2f(lo.x * SM_SCALE); p1 = exp2f(lo.y * SM_SCALE);
                    p2 = exp2f(hi.x * SM_SCALE); p3 = exp2f(hi.y * SM_SCALE);
                }
                __half2 q0 = __floats2half2_rn(p0, p1);
                __half2 q1 = __floats2half2_rn(p2, p3);
                *(uint32_t*)(Ch + (size_t)m0 * ldc + n0)       = *(uint32_t*)&q0;
                *(uint32_t*)(Ch + (size_t)(m0 + 8) * ldc + n0) = *(uint32_t*)&q1;
            } else if (mode == 2) {
                float2 lo = __half22float2(*(__half2*)&acc[mi][nj][0]);
                float2 hi = __half22float2(*(__half2*)&acc[mi][nj][1]);
                *(float2*)(Csplit + (size_t)m0 * ldc + n0)       = lo;
                *(float2*)(Csplit + (size_t)(m0 + 8) * ldc + n0) = hi;
            } else {               // mode 3: transposed fp16
                __half* Ch = (__half*)C;
                __half2 h0 = *(__half2*)&acc[mi][nj][0];
                __half2 h1 = *(__half2*)&acc[mi][nj][1];
                Ch[(size_t)n0 * ldc + m0]           = __low2half(h0);
                Ch[(size_t)(n0 + 1) * ldc + m0]     = __high2half(h0);
                Ch[(size_t)n0 * ldc + m0 + 8]       = __low2half(h1);
                Ch[(size_t)(n0 + 1) * ldc + m0 + 8] = __high2half(h1);
            }
        }
    }
}

// ---------------------------------------------------------------------------
// Epilogue: row-sum of P, self term, split-K combine, normalize, residual, LN.
// One warp per row.
// ---------------------------------------------------------------------------
__global__ __launch_bounds__(256) void epi_kernel(
    const float* __restrict__ v_code,
    const float* __restrict__ gamma,
    const float* __restrict__ beta,
    float* __restrict__ out)
{
    int warp = threadIdx.x >> 5, lane = threadIdx.x & 31;
    int r = blockIdx.x * 8 + warp;

    // sum of P row (fp16 numerators)
    const uint4* Pr = (const uint4*)(g_P + (size_t)r * NM);
    float s = 0.f;
#pragma unroll
    for (int t = 0; t < 16; t++) {
        uint4 u = Pr[lane + 32 * t];
        float2 f0 = __half22float2(*(__half2*)&u.x);
        float2 f1 = __half22float2(*(__half2*)&u.y);
        float2 f2 = __half22float2(*(__half2*)&u.z);
        float2 f3 = __half22float2(*(__half2*)&u.w);
        s += (f0.x + f0.y) + (f1.x + f1.y) + (f2.x + f2.y) + (f3.x + f3.y);
    }
#pragma unroll
    for (int o = 16; o > 0; o >>= 1) s += __shfl_xor_sync(0xffffffffu, s, o);

    // self-attention score q . k (fp16 operands, fp32 math)
    const uint4* q4 = (const uint4*)(g_vqh + (size_t)r * ED);
    const uint4* k4 = (const uint4*)(g_vkh + (size_t)r * ED);
    float sd = 0.f;
#pragma unroll
    for (int t = 0; t < 2; t++) {
        uint4 uq = q4[lane + 32 * t], uk = k4[lane + 32 * t];
        const __half2* hq = (const __half2*)&uq;
        const __half2* hk = (const __half2*)&uk;
#pragma unroll
        for (int j = 0; j < 4; j++) {
            float2 a = __half22float2(hq[j]);
            float2 b = __half22float2(hk[j]);
            sd += a.x * b.x + a.y * b.y;
        }
    }
#pragma unroll
    for (int o = 16; o > 0; o >>= 1) sd += __shfl_xor_sync(0xffffffffu, sd, o);
    float pself = exp2f(sd * SM_SCALE);
    float linv = 1.f / (s + pself);

    const float* vc = v_code + (size_t)r * ED;
    const __half* vv = g_vvh + (size_t)r * ED;

    float vals[16];
    float mu = 0.f;
#pragma unroll
    for (int t = 0; t < 16; t++) {
        int e = lane + 32 * t;
        size_t idx = (size_t)r * ED + e;
        float o4 = g_Opart[0][idx] + g_Opart[1][idx] + g_Opart[2][idx] + g_Opart[3][idx];
        float v = (o4 + pself * __half2float(vv[e])) * linv + vc[e];
        vals[t] = v; mu += v;
    }
#pragma unroll
    for (int o = 16; o > 0; o >>= 1) mu += __shfl_xor_sync(0xffffffffu, mu, o);
    mu *= (1.f / 512.f);
    float var = 0.f;
#pragma unroll
    for (int t = 0; t < 16; t++) { float d = vals[t] - mu; var += d * d; }
#pragma unroll
    for (int o = 16; o > 0; o >>= 1) var += __shfl_xor_sync(0xffffffffu, var, o);
    float rstd = rsqrtf(var * (1.f / 512.f) + 1e-6f);
#pragma unroll
    for (int t = 0; t < 16; t++) {
        int e = lane + 32 * t;
        out[(size_t)r * ED + e] = (vals[t] - mu) * rstd * gamma[e] + beta[e];
    }
}

// ---------------------------------------------------------------------------
extern "C" void kernel_launch(void* const* d_in, const int* in_sizes, int n_in,
                              void* d_out, int out_size)
{
    const float* v_code   = (const float*)d_in[0];
    const float* obs_code = (const float*)d_in[1];
    const float* Wq       = (const float*)d_in[2];
    const float* Wk       = (const float*)d_in[3];
    const float* Wv       = (const float*)d_in[4];
    const float* gamma    = (const float*)d_in[5];
    const float* beta     = (const float*)d_in[6];
    float* out = (float*)d_out;

    __half *vch, *och, *wqh, *wkh, *wvh, *vqh, *vkh, *vvh, *okh, *ovT, *P;
    float* Op;
    cudaGetSymbolAddress((void**)&vch, g_vch);
    cudaGetSymbolAddress((void**)&och, g_och);
    cudaGetSymbolAddress((void**)&wqh, g_wqh);
    cudaGetSymbolAddress((void**)&wkh, g_wkh);
    cudaGetSymbolAddress((void**)&wvh, g_wvh);
    cudaGetSymbolAddress((void**)&vqh, g_vqh);
    cudaGetSymbolAddress((void**)&vkh, g_vkh);
    cudaGetSymbolAddress((void**)&vvh, g_vvh);
    cudaGetSymbolAddress((void**)&okh, g_okh);
    cudaGetSymbolAddress((void**)&ovT, g_ovT);
    cudaGetSymbolAddress((void**)&P,   g_P);
    cudaGetSymbolAddress((void**)&Op,  g_Opart);

    const int smem = 65536;
    cudaFuncSetAttribute(gemm_h, cudaFuncAttributeMaxDynamicSharedMemorySize, smem);
    dim3 blk(256);

    // #0: one fused convert
    int n_cvt = (NQ * ED + NM * ED + 3 * ED * ED) / 4;
    cvt_all<<<(n_cvt + 255) / 256, 256>>>((const float4*)v_code, (const float4*)obs_code,
                                          (const float4*)Wq, (const float4*)Wk, (const float4*)Wv);
    // #1-#3: projections needed by attention
    gemm_h<<<dim3(NQ / 128, 4),  blk, smem>>>(vch, ED, wqh, ED, vqh, ED, ED, 0, 4);
    gemm_h<<<dim3(NM / 128, 4),  blk, smem>>>(och, ED, wkh, ED, okh, ED, ED, 0, 4);
    gemm_h<<<dim3(NM / 128, 4),  blk, smem>>>(och, ED, wvh, ED, ovT, NM, ED, 3, 4);
    // #4: QK^T + fused exp -> P (fp16)
    gemm_h<<<dim3(NQ / 128, 32), blk, smem>>>(vqh, ED, okh, ED, P, NM, ED, 1, 32);
    // #5: P @ ovT^T -> O, split-K x4 (grid.y = 4 n-tiles x 4 splits)
    gemm_h<<<dim3(NQ / 128, 16), blk, smem>>>(P, NM, ovT, NM, Op, ED, NM / 4, 2, 4);
    // #6-#7: remaining projections (epilogue-only consumers)
    gemm_h<<<dim3(NQ / 128, 4),  blk, smem>>>(vch, ED, wkh, ED, vkh, ED, ED, 0, 4);
    gemm_h<<<dim3(NQ / 128, 4),  blk, smem>>>(vch, ED, wvh, ED, vvh, ED, ED, 0, 4);
    // #8: softmax-normalize + residual + layernorm
    epi_kernel<<<NQ / 8, blk>>>(v_code, gamma, beta, out);
}

// round 6
// speedup vs baseline: 12.0019x; 1.0587x over previous
#include <cuda_runtime.h>
#include <cuda_fp16.h>
#include <cstdint>

#define NQ 8192
#define NM 4096
#define ED 512
// log2(e) / TEMPERATURE  (TEMPERATURE = sqrt(512))
#define SM_SCALE (1.4426950408889634f / 22.627416997969522f)

// ---------------- scratch (__device__ globals; no allocs allowed) ----------
__device__ __half g_vch[NQ * ED];
__device__ __half g_och[NM * ED];
__device__ __half g_wall[3 * ED * ED];      // Wq | Wk | Wv rows
__device__ __half g_vqkv[(size_t)NQ * 3 * ED]; // vq|vk|vv per row (stride 1536)
__device__ __half g_okh[NM * ED];
__device__ __half g_ovT[(size_t)ED * NM];   // transposed V-proj of obs
__device__ __half g_P[(size_t)NQ * NM];     // softmax numerators (fp16)
__device__ float g_rs[(size_t)NQ * 32];     // per-(row, n-tile) partial P sums
__device__ float g_Opart[4][NQ * ED];       // split-K partials of O

// ---------------- helpers --------------------------------------------------
__device__ __forceinline__ uint32_t smem_u32(const void* p) {
    uint32_t a;
    asm("{ .reg .u64 t; cvta.to.shared.u64 t, %1; cvt.u32.u64 %0, t; }" : "=r"(a) : "l"(p));
    return a;
}

#define LDM4(r, addr) \
    asm volatile("ldmatrix.sync.aligned.m8n8.x4.shared.b16 {%0,%1,%2,%3}, [%4];" \
        : "=r"((r)[0]), "=r"((r)[1]), "=r"((r)[2]), "=r"((r)[3]) : "r"(addr))

// fp16 accumulate MMA
#define MMAH(d, a, b0, b1) \
    asm volatile("mma.sync.aligned.m16n8k16.row.col.f16.f16.f16.f16 " \
        "{%0,%1}, {%2,%3,%4,%5}, {%6,%7}, {%0,%1};" \
        : "+r"((d)[0]), "+r"((d)[1]) \
        : "r"((a)[0]), "r"((a)[1]), "r"((a)[2]), "r"((a)[3]), "r"(b0), "r"(b1))

// quartic exp2 on the FMA pipe (|rel err| < 5e-5 on the needed range)
__device__ __forceinline__ float fast_exp2(float x) {
    float t = x + 12582912.f;                 // round-to-nearest-int trick
    float fl = t - 12582912.f;
    float f = x - fl;                         // f in [-0.5, 0.5]
    int n = __float_as_int(t) - 0x4B400000;   // signed integer part
    float p = fmaf(fmaf(fmaf(fmaf(0.0096181291f, f, 0.0555041087f),
                             f, 0.2402265070f), f, 0.6931471806f), f, 1.0f);
    return __int_as_float(__float_as_int(p) + (n << 23));
}

// load one 128x64 fp16 tile pair (A,B) into SW128-swizzled smem via cp.async
__device__ __forceinline__ void load_tiles_h(uint32_t ab, uint32_t bb,
    const __half* __restrict__ Ag, int lda,
    const __half* __restrict__ Bg, int ldb, int tid)
{
    int c  = tid & 7;
    int r0 = tid >> 3;
#pragma unroll
    for (int it = 0; it < 4; it++) {
        int row = r0 + it * 32;
        uint32_t off = (uint32_t)(row * 128 + ((c << 4) ^ ((row & 7) << 4)));
        asm volatile("cp.async.cg.shared.global [%0], [%1], 16;"
            :: "r"(ab + off), "l"(Ag + (size_t)row * lda + c * 8) : "memory");
        asm volatile("cp.async.cg.shared.global [%0], [%1], 16;"
            :: "r"(bb + off), "l"(Bg + (size_t)row * ldb + c * 8) : "memory");
    }
    asm volatile("cp.async.commit_group;" ::: "memory");
}

// ---------------------------------------------------------------------------
// fp32 -> fp16 conversion of all inputs in ONE launch (weights concatenated)
// ---------------------------------------------------------------------------
__global__ __launch_bounds__(256) void cvt_all(
    const float4* __restrict__ vc, const float4* __restrict__ oc,
    const float4* __restrict__ wq, const float4* __restrict__ wk,
    const float4* __restrict__ wv)
{
    const int n_vc = NQ * ED / 4, n_oc = NM * ED / 4, n_w = ED * ED / 4;
    int i = blockIdx.x * 256 + threadIdx.x;
    const float4* s; uint2* d; int j;
    if (i < n_vc)                      { s = vc; d = (uint2*)g_vch;  j = i; }
    else if (i < n_vc + n_oc)          { s = oc; d = (uint2*)g_och;  j = i - n_vc; }
    else if (i < n_vc + n_oc + n_w)    { s = wq; d = (uint2*)g_wall; j = i - n_vc - n_oc; }
    else if (i < n_vc + n_oc + 2*n_w)  { s = wk; d = (uint2*)g_wall + n_w; j = i - n_vc - n_oc - n_w; }
    else if (i < n_vc + n_oc + 3*n_w)  { s = wv; d = (uint2*)g_wall + 2*n_w; j = i - n_vc - n_oc - 2*n_w; }
    else return;
    float4 v = s[j];
    __half2 a = __floats2half2_rn(v.x, v.y);
    __half2 b = __floats2half2_rn(v.z, v.w);
    d[j] = make_uint2(*(uint32_t*)&a, *(uint32_t*)&b);
}

// ---------------------------------------------------------------------------
// fp16 GEMM via mma.sync (f16 acc): D[128,128] = A[128,K] @ B[128,K]^T.
// 256 threads, warp grid 2x4, warp tile 64x32, BK=64, double buffered.
// mode 0: store fp16 row-major
// mode 1: exp2(x*SM_SCALE)->fp16 row-major + per-row partial sums -> g_rs
// mode 2: store fp32 row-major (split-K partial)
// mode 4: obs fused: n<512 -> g_okh normal; n>=512 -> g_ovT transposed
// nsy: #n-tiles in gridDim.y; blocks beyond that are split-K slices.
// ---------------------------------------------------------------------------
__global__ __launch_bounds__(256) void gemm_h(
    const __half* __restrict__ A, int lda,
    const __half* __restrict__ B, int ldb,
    void* __restrict__ C, int ldc, int K, int mode, int nsy)
{
    extern __shared__ char smem_raw[];
    uint32_t sb = smem_u32(smem_raw);

    const int tid = threadIdx.x;
    const int lane = tid & 31, wid = tid >> 5;
    const int wm = wid >> 2, wn = wid & 3;       // warp grid 2x4
    const int split = blockIdx.y / nsy;
    const int bm = blockIdx.x * 128, bn = (blockIdx.y % nsy) * 128;
    const int nc = K >> 6;

    A += (size_t)split * K;                      // split-K column offset
    B += (size_t)split * K;
    float* Csplit = (float*)C + (size_t)split * ((size_t)gridDim.x * 128) * ldc;

    const __half* Abase = A + (size_t)bm * lda;
    const __half* Bbase = B + (size_t)bn * ldb;

    load_tiles_h(sb, sb + 16384, Abase, lda, Bbase, ldb, tid);
    if (nc > 1)
        load_tiles_h(sb + 32768, sb + 49152, Abase + 64, lda, Bbase + 64, ldb, tid);

    uint32_t acc[4][4][2];
#pragma unroll
    for (int i = 0; i < 4; i++)
#pragma unroll
        for (int j = 0; j < 4; j++) { acc[i][j][0] = 0u; acc[i][j][1] = 0u; }

    uint32_t a_rb[4], a_p[4], b_rb[2], b_p[2];
#pragma unroll
    for (int mi = 0; mi < 4; mi++) {
        int row = wm * 64 + mi * 16 + (lane & 15);
        a_rb[mi] = (uint32_t)(row * 128);
        a_p[mi]  = (uint32_t)((row & 7) << 4);
    }
#pragma unroll
    for (int nb = 0; nb < 2; nb++) {
        int row = wn * 32 + nb * 16 + (lane & 15);
        b_rb[nb] = (uint32_t)(row * 128);
        b_p[nb]  = (uint32_t)((row & 7) << 4);
    }
    const uint32_t h16 = (uint32_t)((lane >> 4) << 4);

    for (int i = 0; i < nc; i++) {
        int s = i & 1;
        if (i + 1 < nc) asm volatile("cp.async.wait_group 1;" ::: "memory");
        else            asm volatile("cp.async.wait_group 0;" ::: "memory");
        __syncthreads();

        uint32_t ab = sb + s * 32768;
        uint32_t bb = ab + 16384;
#pragma unroll
        for (int ks = 0; ks < 4; ks++) {
            uint32_t kh = (uint32_t)(ks << 5) | h16;
            uint32_t af[4][4], bf[2][4];
#pragma unroll
            for (int mi = 0; mi < 4; mi++)
                LDM4(af[mi], ab + a_rb[mi] + (kh ^ a_p[mi]));
#pragma unroll
            for (int nb = 0; nb < 2; nb++)
                LDM4(bf[nb], bb + b_rb[nb] + (kh ^ b_p[nb]));
#pragma unroll
            for (int mi = 0; mi < 4; mi++) {
#pragma unroll
                for (int nb = 0; nb < 2; nb++) {
                    MMAH(acc[mi][nb * 2 + 0], af[mi], bf[nb][0], bf[nb][2]);
                    MMAH(acc[mi][nb * 2 + 1], af[mi], bf[nb][1], bf[nb][3]);
                }
            }
        }
        __syncthreads();
        if (i + 2 < nc)
            load_tiles_h(ab, bb, Abase + (i + 2) * 64, lda, Bbase + (i + 2) * 64, ldb, tid);
    }

    // ---- epilogue straight from registers ---------------------------------
    const int g = lane >> 2, tg = lane & 3;
    float rs[4][2];
#pragma unroll
    for (int mi = 0; mi < 4; mi++) { rs[mi][0] = 0.f; rs[mi][1] = 0.f; }

#pragma unroll
    for (int mi = 0; mi < 4; mi++) {
#pragma unroll
        for (int nj = 0; nj < 4; nj++) {
            int m0 = bm + wm * 64 + mi * 16 + g;
            int n0 = bn + wn * 32 + nj * 8 + tg * 2;
            if (mode == 0) {
                __half* Ch = (__half*)C;
                *(uint32_t*)(Ch + (size_t)m0 * ldc + n0)       = acc[mi][nj][0];
                *(uint32_t*)(Ch + (size_t)(m0 + 8) * ldc + n0) = acc[mi][nj][1];
            } else if (mode == 1) {
                __half* Ch = (__half*)C;
                float2 lo = __half22float2(*(__half2*)&acc[mi][nj][0]);
                float2 hi = __half22float2(*(__half2*)&acc[mi][nj][1]);
                float p0 = fast_exp2(lo.x * SM_SCALE);
                float p1 = fast_exp2(lo.y * SM_SCALE);
                float p2 = fast_exp2(hi.x * SM_SCALE);
                float p3 = fast_exp2(hi.y * SM_SCALE);
                rs[mi][0] += p0 + p1;
                rs[mi][1] += p2 + p3;
                __half2 q0 = __floats2half2_rn(p0, p1);
                __half2 q1 = __floats2half2_rn(p2, p3);
                *(uint32_t*)(Ch + (size_t)m0 * ldc + n0)       = *(uint32_t*)&q0;
                *(uint32_t*)(Ch + (size_t)(m0 + 8) * ldc + n0) = *(uint32_t*)&q1;
            } else if (mode == 2) {
                float2 lo = __half22float2(*(__half2*)&acc[mi][nj][0]);
                float2 hi = __half22float2(*(__half2*)&acc[mi][nj][1]);
                *(float2*)(Csplit + (size_t)m0 * ldc + n0)       = lo;
                *(float2*)(Csplit + (size_t)(m0 + 8) * ldc + n0) = hi;
            } else {               // mode 4: obs fused proj
                if (bn < 512) {    // ok: normal fp16, ldc = 512
                    __half* Ch = g_okh;
                    *(uint32_t*)(Ch + (size_t)m0 * ED + n0)       = acc[mi][nj][0];
                    *(uint32_t*)(Ch + (size_t)(m0 + 8) * ED + n0) = acc[mi][nj][1];
                } else {           // ov: transposed into g_ovT[e][kv]
                    int e0 = n0 - 512;
                    __half2 h0 = *(__half2*)&acc[mi][nj][0];
                    __half2 h1 = *(__half2*)&acc[mi][nj][1];
                    g_ovT[(size_t)e0 * NM + m0]           = __low2half(h0);
                    g_ovT[(size_t)(e0 + 1) * NM + m0]     = __high2half(h0);
                    g_ovT[(size_t)e0 * NM + m0 + 8]       = __low2half(h1);
                    g_ovT[(size_t)(e0 + 1) * NM + m0 + 8] = __high2half(h1);
                }
            }
        }
    }

    // ---- mode 1: deterministic per-row partial sum reduction --------------
    if (mode == 1) {
#pragma unroll
        for (int mi = 0; mi < 4; mi++) {
#pragma unroll
            for (int h = 0; h < 2; h++) {
                rs[mi][h] += __shfl_xor_sync(0xffffffffu, rs[mi][h], 1);
                rs[mi][h] += __shfl_xor_sync(0xffffffffu, rs[mi][h], 2);
            }
        }
        float* ps = (float*)smem_raw;            // reuse tile smem (all warps past final barrier)
        if (tg == 0) {
#pragma unroll
            for (int mi = 0; mi < 4; mi++) {
                ps[wn * 128 + wm * 64 + mi * 16 + g]     = rs[mi][0];
                ps[wn * 128 + wm * 64 + mi * 16 + g + 8] = rs[mi][1];
            }
        }
        __syncthreads();
        if (tid < 128) {
            float v = ps[tid] + ps[128 + tid] + ps[256 + tid] + ps[384 + tid];
            g_rs[(size_t)(bm + tid) * 32 + (bn >> 7)] = v;
        }
    }
}

// ---------------------------------------------------------------------------
// Epilogue: combine row sums, self term, split-K combine, normalize,
// residual, layernorm. One warp per row.
// ---------------------------------------------------------------------------
__global__ __launch_bounds__(256) void epi_kernel(
    const float* __restrict__ v_code,
    const float* __restrict__ gamma,
    const float* __restrict__ beta,
    float* __restrict__ out)
{
    int warp = threadIdx.x >> 5, lane = threadIdx.x & 31;
    int r = blockIdx.x * 8 + warp;

    // P row sum from qk partials (one per n-tile)
    float s = g_rs[(size_t)r * 32 + lane];
#pragma unroll
    for (int o = 16; o > 0; o >>= 1) s += __shfl_xor_sync(0xffffffffu, s, o);

    // self-attention score q . k (fp16 operands, fp32 math)
    const uint4* q4 = (const uint4*)(g_vqkv + (size_t)r * 1536);
    const uint4* k4 = (const uint4*)(g_vqkv + (size_t)r * 1536 + 512);
    float sd = 0.f;
#pragma unroll
    for (int t = 0; t < 2; t++) {
        uint4 uq = q4[lane + 32 * t], uk = k4[lane + 32 * t];
        const __half2* hq = (const __half2*)&uq;
        const __half2* hk = (const __half2*)&uk;
#pragma unroll
        for (int j = 0; j < 4; j++) {
            float2 a = __half22float2(hq[j]);
            float2 b = __half22float2(hk[j]);
            sd += a.x * b.x + a.y * b.y;
        }
    }
#pragma unroll
    for (int o = 16; o > 0; o >>= 1) sd += __shfl_xor_sync(0xffffffffu, sd, o);
    float pself = exp2f(sd * SM_SCALE);
    float linv = 1.f / (s + pself);

    const float* vc = v_code + (size_t)r * ED;
    const __half* vv = g_vqkv + (size_t)r * 1536 + 1024;

    float vals[16];
    float mu = 0.f;
#pragma unroll
    for (int t = 0; t < 16; t++) {
        int e = lane + 32 * t;
        size_t idx = (size_t)r * ED + e;
        float o4 = g_Opart[0][idx] + g_Opart[1][idx] + g_Opart[2][idx] + g_Opart[3][idx];
        float v = (o4 + pself * __half2float(vv[e])) * linv + vc[e];
        vals[t] = v; mu += v;
    }
#pragma unroll
    for (int o = 16; o > 0; o >>= 1) mu += __shfl_xor_sync(0xffffffffu, mu, o);
    mu *= (1.f / 512.f);
    float var = 0.f;
#pragma unroll
    for (int t = 0; t < 16; t++) { float d = vals[t] - mu; var += d * d; }
#pragma unroll
    for (int o = 16; o > 0; o >>= 1) var += __shfl_xor_sync(0xffffffffu, var, o);
    float rstd = rsqrtf(var * (1.f / 512.f) + 1e-6f);
#pragma unroll
    for (int t = 0; t < 16; t++) {
        int e = lane + 32 * t;
        out[(size_t)r * ED + e] = (vals[t] - mu) * rstd * gamma[e] + beta[e];
    }
}

// ---------------------------------------------------------------------------
extern "C" void kernel_launch(void* const* d_in, const int* in_sizes, int n_in,
                              void* d_out, int out_size)
{
    const float* v_code   = (const float*)d_in[0];
    const float* obs_code = (const float*)d_in[1];
    const float* Wq       = (const float*)d_in[2];
    const float* Wk       = (const float*)d_in[3];
    const float* Wv       = (const float*)d_in[4];
    const float* gamma    = (const float*)d_in[5];
    const float* beta     = (const float*)d_in[6];
    float* out = (float*)d_out;

    __half *vch, *och, *wall, *vqkv, *okh, *ovT, *P;
    float* Op;
    cudaGetSymbolAddress((void**)&vch,  g_vch);
    cudaGetSymbolAddress((void**)&och,  g_och);
    cudaGetSymbolAddress((void**)&wall, g_wall);
    cudaGetSymbolAddress((void**)&vqkv, g_vqkv);
    cudaGetSymbolAddress((void**)&okh,  g_okh);
    cudaGetSymbolAddress((void**)&ovT,  g_ovT);
    cudaGetSymbolAddress((void**)&P,    g_P);
    cudaGetSymbolAddress((void**)&Op,   g_Opart);

    const int smem = 65536;
    cudaFuncSetAttribute(gemm_h, cudaFuncAttributeMaxDynamicSharedMemorySize, smem);
    dim3 blk(256);

    // #0: one fused convert (weights concatenated into g_wall)
    int n_cvt = (NQ * ED + NM * ED + 3 * ED * ED) / 4;
    cvt_all<<<(n_cvt + 255) / 256, 256>>>((const float4*)v_code, (const float4*)obs_code,
                                          (const float4*)Wq, (const float4*)Wk, (const float4*)Wv);
    // #1: fused v_code projection -> g_vqkv [8192, 1536]
    gemm_h<<<dim3(NQ / 128, 12), blk, smem>>>(vch, ED, wall, ED, vqkv, 3 * ED, ED, 0, 12);
    // #2: fused obs projection -> g_okh + g_ovT (weights Wk|Wv)
    gemm_h<<<dim3(NM / 128, 8),  blk, smem>>>(och, ED, wall + ED * ED, ED, nullptr, 0, ED, 4, 8);
    // #3: QK^T + fused exp + row-sum partials -> P (fp16), g_rs
    gemm_h<<<dim3(NQ / 128, 32), blk, smem>>>(vqkv, 3 * ED, okh, ED, P, NM, ED, 1, 32);
    // #4: P @ ovT^T -> O, split-K x4
    gemm_h<<<dim3(NQ / 128, 16), blk, smem>>>(P, NM, ovT, NM, Op, ED, NM / 4, 2, 4);
    // #5: softmax-normalize + residual + layernorm
    epi_kernel<<<NQ / 8, blk>>>(v_code, gamma, beta, out);
}